// round 11
// baseline (speedup 1.0000x reference)
#include <cuda_runtime.h>
#include <math.h>

// ---------------- problem constants ----------------
#define BATCH 2
#define NCLS 24
#define NHEADS 8
#define CIN0 1024
#define CPROJ 128

typedef unsigned long long ull;

// ---------------- scratch (static device memory; no allocs) ----------------
__device__ __align__(16) float g_wproj[(size_t)BATCH * NHEADS * CPROJ * CIN0];
__device__ __align__(16) float g_t0[(size_t)BATCH * 1024 * 4 * 6 * 8];
__device__ __align__(16) float g_t1[(size_t)BATCH * 512 * 8 * 12 * 16];
__device__ __align__(16) float g_t2[(size_t)BATCH * 256 * 16 * 24 * 32];
__device__ __align__(16) float g_t3[(size_t)BATCH * 128 * 32 * 48 * 64];
__device__ __align__(16) float g_t4[(size_t)BATCH * 32 * 64 * 96 * 128];
__device__ __align__(16) float g_pL1[(size_t)4 * 512 * 8 * 12 * 16];  // 2 splits x B x C x S
__device__ __align__(16) float g_part[1024 * 16 * 2];
__device__ __align__(16) float g_scale[1024];
__device__ __align__(16) float g_shift[1024];

// ---------------- packed f32x2 helpers (register-only) ----------------
__device__ __forceinline__ void fma2(ull& d, ull a, ull b) {
    asm("fma.rn.f32x2 %0, %1, %2, %0;" : "+l"(d) : "l"(a), "l"(b));
}
__device__ __forceinline__ ull pack2f(float lo, float hi) {
    ull r;
    asm("mov.b64 %0, {%1, %2};" : "=l"(r) : "f"(lo), "f"(hi));
    return r;
}
__device__ __forceinline__ float2 unpk2(ull v) {
    float2 r;
    asm("mov.b64 {%0, %1}, %2;" : "=f"(r.x), "=f"(r.y) : "l"(v));
    return r;
}

// ---------------- hypernet ----------------
__global__ void hyper_kernel(const float* __restrict__ y,
                             const float* __restrict__ tables,
                             float* __restrict__ wout) {
    const int K = CPROJ * CIN0;
    int gid = blockIdx.x * blockDim.x + threadIdx.x;
    if (gid >= NHEADS * K) return;
    int h = gid / K;
    int k = gid - h * K;
    const float* t = tables + (size_t)h * NCLS * K + k;
    float a0 = 0.f, a1 = 0.f;
#pragma unroll
    for (int q = 0; q < NCLS; q++) {
        float tv = t[(size_t)q * K];
        a0 += y[q] * tv;
        a1 += y[NCLS + q] * tv;
    }
    wout[(size_t)0 * NHEADS * K + gid] = a0;
    wout[(size_t)1 * NHEADS * K + gid] = a1;
}

// ---------------- projection (smem-tiled, 8 out-rows per block) ----------------
__global__ void proj_kernel2(const float* __restrict__ x,
                             const float* __restrict__ w,
                             float* __restrict__ out) {
    const int S = 192;
    const int s = threadIdx.x;
    const int hb = blockIdx.x;
    const int b = blockIdx.y;
    const float* xb = x + (size_t)b * 1024 * S + s;
    const float* wb = w + ((size_t)b * 1024 + hb * 8) * 1024;

    __shared__ float wsh[8][192];
    float acc[8];
#pragma unroll
    for (int j = 0; j < 8; j++) acc[j] = 0.f;

    for (int c0 = 0; c0 < 1024; c0 += 192) {
        __syncthreads();
        int cmax = 1024 - c0 < 192 ? 1024 - c0 : 192;
        if (s < cmax) {
#pragma unroll
            for (int j = 0; j < 8; j++) wsh[j][s] = wb[(size_t)j * 1024 + c0 + s];
        }
        __syncthreads();
        for (int cc = 0; cc < cmax; cc++) {
            float xv = xb[(size_t)(c0 + cc) * S];
#pragma unroll
            for (int j = 0; j < 8; j++) acc[j] = fmaf(wsh[j][cc], xv, acc[j]);
        }
    }
#pragma unroll
    for (int j = 0; j < 8; j++)
        out[((size_t)b * 1024 + hb * 8 + j) * S + s] = acc[j];
}

// ---------------- BatchNorm ----------------
#define BN_NB 16
__global__ void bn_partial(const float* __restrict__ x, int C, int S,
                           float* __restrict__ part) {
    int c = blockIdx.x;
    int nb = blockIdx.y;
    int n = BATCH * S;
    float s1 = 0.f, s2 = 0.f;
    for (int e = nb * blockDim.x + threadIdx.x; e < n; e += BN_NB * blockDim.x) {
        int bb = e / S;
        int sp = e - bb * S;
        float v = x[((size_t)bb * C + c) * S + sp];
        s1 += v;
        s2 += v * v;
    }
    __shared__ float r1[256];
    __shared__ float r2[256];
    r1[threadIdx.x] = s1;
    r2[threadIdx.x] = s2;
    __syncthreads();
    for (int st = 128; st > 0; st >>= 1) {
        if (threadIdx.x < st) {
            r1[threadIdx.x] += r1[threadIdx.x + st];
            r2[threadIdx.x] += r2[threadIdx.x + st];
        }
        __syncthreads();
    }
    if (threadIdx.x == 0) {
        part[(c * BN_NB + nb) * 2 + 0] = r1[0];
        part[(c * BN_NB + nb) * 2 + 1] = r2[0];
    }
}

__global__ void bn_finalize(const float* __restrict__ part, int C, float n,
                            const float* __restrict__ g, const float* __restrict__ be,
                            float* __restrict__ scale, float* __restrict__ shift) {
    int c = blockIdx.x * blockDim.x + threadIdx.x;
    if (c >= C) return;
    float s1 = 0.f, s2 = 0.f;
    for (int i = 0; i < BN_NB; i++) {
        s1 += part[(c * BN_NB + i) * 2 + 0];
        s2 += part[(c * BN_NB + i) * 2 + 1];
    }
    float mean = s1 / n;
    float var = s2 / n - mean * mean;
    var = fmaxf(var, 0.f);
    float sc = g[c] * rsqrtf(var + 1e-5f);
    scale[c] = sc;
    shift[c] = be[c] - mean * sc;
}

__global__ void bn_apply_relu(float* __restrict__ x, int C, int S,
                              const float* __restrict__ scale,
                              const float* __restrict__ shift) {
    size_t gid = (size_t)blockIdx.x * blockDim.x + threadIdx.x;
    size_t total = (size_t)BATCH * C * S;
    if (gid >= total) return;
    int c = (int)((gid / S) % C);
    float v = fmaf(x[gid], scale[c], shift[c]);
    x[gid] = v > 0.f ? v : 0.f;
}

// ---------------- L1 partial combine: t1 = p[split0] + p[split1] + bias ------
__global__ void combine_kernel(const float* __restrict__ p,
                               const float* __restrict__ bias,
                               float* __restrict__ outp, int Cout, int OS) {
    size_t gid = (size_t)blockIdx.x * blockDim.x + threadIdx.x;
    size_t per_b = (size_t)Cout * OS;
    size_t total = (size_t)BATCH * per_b;
    if (gid >= total) return;
    int b = (int)(gid / per_b);
    size_t r = gid - (size_t)b * per_b;
    int c = (int)(r / OS);
    outp[gid] = p[(size_t)(2 * b) * per_b + r] + p[(size_t)(2 * b + 1) * per_b + r] +
                bias[c];
}

// ---------------- ConvTranspose3d k=4 s=2 p=1 : dual-copy smem + LDS.128 w ----
// Per dim: out px=0 taps (d=0,k=1),(d=-1,k=3) ; px=1 taps (d=+1,k=0),(d=0,k=2).
// Staged tile: copy A = natural halo row h[0..TILEX+1], copy B = h shifted by 1.
// f32x2 operands are direct LDS.64: (h2t,h2t+1)=A[t], (h2t+1,h2t+2)=B[t],
// (h2t+2,h2t+3)=A[t+1]. Weights: one ulonglong2 LDS.128 = (w1,w0)|(w3,w2).
// NSPLIT>1: input channels split across blockIdx.z into partial outputs, no bias.
template <int TILEY, int TILEX, int RWF, int OG, int OC, int CC, int NSPLIT,
          bool SIG>
__global__ void __launch_bounds__(TILEY * TILEX * OG)
convt9_kernel(const float* __restrict__ in, const float* __restrict__ wt,
              const float* __restrict__ bias, float* __restrict__ out,
              int Cin, int Cout, int Dz, int Hy, int Wx, int ntx, int nty) {
    constexpr int TXc = TILEX / 2;
    constexpr int TYc = TILEY / 2;
    constexpr int NTS = TILEY * TILEX;
    constexpr int NT = NTS * OG;
    constexpr int PH = TILEY + 2;
    constexpr int RWA = RWF / 2;           // row pitch in ull
    constexpr int ASZ = 6 * PH * RWF;      // one copy, floats (even)
    constexpr int VSZ = 2 * ASZ;           // A + B copies
    constexpr int RMAX = (ASZ + NT - 1) / NT;
    constexpr int WN = OG * OC * CC * 16;  // ulonglong2 entries per chunk

    __shared__ __align__(16) float vsm[2][VSZ];
    __shared__ __align__(16) ulonglong2 wsm2[2][WN];

    const int tid = threadIdx.x;
    const int og = tid / NTS;
    const int s = tid - og * NTS;
    const int obase = blockIdx.y * OG * OC + og * OC;
    const int zid = blockIdx.z;
    const int b = zid / NSPLIT;
    const int CLEN = Cin / NSPLIT;
    const int cbeg = (zid - b * NSPLIT) * CLEN;
    const int tile = blockIdx.x;
    const int tix = tile % ntx;
    const int t2 = tile / ntx;
    const int tiy = t2 % nty;
    const int tiz = t2 / nty;

    const int txi = s % TXc;
    const int t3 = s / TXc;
    const int tyi = t3 % TYc;
    const int tzi = t3 / TYc;  // 0..3

    const int bz = tiz * 4, by = tiy * TILEY, bx = tix * TILEX;
    const int S = Dz * Hy * Wx;
    const float* inb = in + (size_t)b * Cin * S;

    // channel-invariant staging offsets (A-linear index); masks for act/B/valid
    int soff[RMAX];
    unsigned m_act = 0, m_hasB = 0, m_vld = 0;
#pragma unroll
    for (int r = 0; r < RMAX; r++) {
        int idx = tid + r * NT;
        int i2 = idx < ASZ ? idx : 0;
        int plane = i2 / (PH * RWF);
        int rem = i2 - plane * (PH * RWF);
        int row = rem / RWF;
        int col = rem - row * RWF;
        bool act = (idx < ASZ) && (col <= TILEX + 1);
        bool hasB = act && (col >= 1);
        int gz = bz + plane - 1, gy = by + row - 1, gx = bx + col - 1;
        bool vld = act && (gz >= 0 && gz < Dz) && (gy >= 0 && gy < Hy) &&
                   (gx >= 0 && gx < Wx);
        if (act) m_act |= 1u << r;
        if (hasB) m_hasB |= 1u << r;
        if (vld) m_vld |= 1u << r;
        soff[r] = vld ? (gz * Hy + gy) * Wx + gx : 0;
    }

    auto stage_w = [&](int chunk) {  // chunk = absolute channel chunk
        ulonglong2* wd = wsm2[chunk & 1];
        for (int i = tid; i < WN; i += NT) {
            int ogc = i / (CC * 16);
            int r = i - ogc * (CC * 16);
            int cl = r >> 4;
            int kk = r & 15;
            const float* wk = wt +
                (((size_t)(chunk * CC + cl)) * Cout +
                 (blockIdx.y * OG * OC + ogc)) * 64 +
                kk * 4;
            ulonglong2 p;
            p.x = pack2f(wk[1], wk[0]);
            p.y = pack2f(wk[3], wk[2]);
            wd[i] = p;
        }
    };

    ull acc[OC][2][2][4];
#pragma unroll
    for (int oc = 0; oc < OC; oc++)
#pragma unroll
        for (int cy = 0; cy < 2; cy++)
#pragma unroll
            for (int cx = 0; cx < 2; cx++)
#pragma unroll
                for (int p = 0; p < 4; p++) acc[oc][cy][cx][p] = 0ull;

    // initial staging (first channel of this split)
    stage_w(cbeg / CC);
    {
        float* vb = vsm[0];
        const float* pc = inb + (size_t)cbeg * S;
#pragma unroll
        for (int r = 0; r < RMAX; r++) {
            if ((m_act >> r) & 1u) {
                int idx = tid + r * NT;
                float v = ((m_vld >> r) & 1u) ? pc[soff[r]] : 0.f;
                vb[idx] = v;
                if ((m_hasB >> r) & 1u) vb[ASZ + idx - 1] = v;
            }
        }
    }
    __syncthreads();

    const int DDt[2][2] = {{0, -1}, {1, 0}};
    const int KKt[2][2] = {{1, 3}, {0, 2}};
    const int tb_base = (2 * tyi) * RWA + txi;  // ull units, plane added per jz

    for (int ci = 0; ci < CLEN; ci++) {
        const int c = cbeg + ci;
        if ((ci & (CC - 1)) == 0 && ci + CC < CLEN) stage_w(c / CC + 1);

        // prefetch next channel into registers
        float pref[RMAX];
        const bool havenext = (ci + 1 < CLEN);
        if (havenext) {
            const float* pc = inb + (size_t)(c + 1) * S;
#pragma unroll
            for (int r = 0; r < RMAX; r++) {
                pref[r] = ((m_vld >> r) & 1u) ? pc[soff[r]] : 0.f;
            }
        }

        const ull* vu = (const ull*)vsm[ci & 1];
        const ulonglong2* wc2 =
            wsm2[(c / CC) & 1] + (og * OC) * CC * 16 + (ci & (CC - 1)) * 16;

#pragma unroll
        for (int jz = 0; jz < 3; jz++) {
            ull vp[4][3];
#pragma unroll
            for (int ry = 0; ry < 4; ry++) {
                int tA = (tzi + jz) * (PH * RWA) + tb_base + ry * RWA;
                vp[ry][0] = vu[tA];
                vp[ry][1] = vu[ASZ / 2 + tA];
                vp[ry][2] = vu[tA + 1];
            }
#pragma unroll
            for (int pz = 0; pz < 2; pz++)
#pragma unroll
                for (int sz = 0; sz < 2; sz++) {
                    if (1 + DDt[pz][sz] != jz) continue;  // compile-time pruned
                    const int kz = KKt[pz][sz];
#pragma unroll
                    for (int py = 0; py < 2; py++)
#pragma unroll
                        for (int sy = 0; sy < 2; sy++) {
                            const int jy0 = 1 + DDt[py][sy];
                            const int ky = KKt[py][sy];
#pragma unroll
                            for (int oc = 0; oc < OC; oc++) {
                                const ulonglong2 w2 = wc2[oc * CC * 16 + kz * 4 + ky];
#pragma unroll
                                for (int cy = 0; cy < 2; cy++) {
                                    const int row = jy0 + cy;
#pragma unroll
                                    for (int cx = 0; cx < 2; cx++) {
                                        fma2(acc[oc][cy][cx][pz * 2 + py],
                                             vp[row][cx + 1], w2.x);
                                        fma2(acc[oc][cy][cx][pz * 2 + py],
                                             vp[row][cx], w2.y);
                                    }
                                }
                            }
                        }
                }
        }

        if (havenext) {
            float* vb1 = vsm[(ci + 1) & 1];
#pragma unroll
            for (int r = 0; r < RMAX; r++) {
                if ((m_act >> r) & 1u) {
                    int idx = tid + r * NT;
                    vb1[idx] = pref[r];
                    if ((m_hasB >> r) & 1u) vb1[ASZ + idx - 1] = pref[r];
                }
            }
        }
        __syncthreads();
    }

    // ---------------- epilogue (scalar stores; exact tiling) ----------------
    const int mz = bz + tzi;
    if (mz >= Dz) return;
    const int Ho = 2 * Hy, Wo = 2 * Wx;
    const int my0 = by + 2 * tyi;
    const int mx0 = bx + 2 * txi;

#pragma unroll
    for (int oc = 0; oc < OC; oc++) {
        const int o = obase + oc;
        const float bv = (NSPLIT > 1) ? 0.f : bias[o];
        float* ob = out + ((size_t)zid * Cout + o) * (size_t)(2 * Dz) * Ho * Wo;
#pragma unroll
        for (int cy = 0; cy < 2; cy++) {
            int my = my0 + cy;
            if (my >= Hy) continue;
#pragma unroll
            for (int cx = 0; cx < 2; cx++) {
                int mx = mx0 + cx;
                if (mx >= Wx) continue;
#pragma unroll
                for (int pz = 0; pz < 2; pz++)
#pragma unroll
                    for (int py = 0; py < 2; py++) {
                        float2 a = unpk2(acc[oc][cy][cx][pz * 2 + py]);
                        float r0 = a.x + bv;
                        float r1 = a.y + bv;
                        if (SIG) {
                            r0 = 1.f / (1.f + __expf(-r0));
                            r1 = 1.f / (1.f + __expf(-r1));
                        }
                        size_t base = (size_t)(2 * mz + pz) * Ho * Wo +
                                      (size_t)(2 * my + py) * Wo + (size_t)(2 * mx);
                        ob[base] = r0;
                        ob[base + 1] = r1;
                    }
            }
        }
    }
}

// ---------------- host-side helpers ----------------
static void run_bn(float* t, int C, int S, const float* g, const float* be,
                   float* part, float* scale, float* shift) {
    dim3 gp(C, BN_NB);
    bn_partial<<<gp, 256>>>(t, C, S, part);
    bn_finalize<<<(C + 127) / 128, 128>>>(part, C, (float)(BATCH * S), g, be, scale, shift);
    size_t total = (size_t)BATCH * C * S;
    bn_apply_relu<<<(unsigned)((total + 255) / 256), 256>>>(t, C, S, scale, shift);
}

template <int TILEY, int TILEX, int RWF, int OG, int OC, int CC, int NSPLIT,
          bool SIG>
static void run_convt9(const float* in, const float* wt, const float* bias,
                       float* out, int Cin, int Cout, int Dz, int Hy, int Wx) {
    int ntx = Wx / TILEX;
    int nty = Hy / TILEY;
    int ntz = Dz / 4;
    dim3 grid(ntx * nty * ntz, Cout / (OG * OC), BATCH * NSPLIT);
    convt9_kernel<TILEY, TILEX, RWF, OG, OC, CC, NSPLIT, SIG>
        <<<grid, TILEY * TILEX * OG>>>(in, wt, bias, out, Cin, Cout, Dz, Hy, Wx,
                                       ntx, nty);
}

extern "C" void kernel_launch(void* const* d_in, const int* in_sizes, int n_in,
                              void* d_out, int out_size) {
    const float* x_in = (const float*)d_in[0];
    const float* y_in = (const float*)d_in[1];
    const float* tables = (const float*)d_in[2];
    const float* g0 = (const float*)d_in[3];
    const float* be0 = (const float*)d_in[4];
    const float* g1 = (const float*)d_in[5];
    const float* be1 = (const float*)d_in[6];
    const float* g2 = (const float*)d_in[7];
    const float* be2 = (const float*)d_in[8];
    const float* g3 = (const float*)d_in[9];
    const float* be3 = (const float*)d_in[10];
    const float* g4 = (const float*)d_in[11];
    const float* be4 = (const float*)d_in[12];
    const float* w1 = (const float*)d_in[13];
    const float* b1 = (const float*)d_in[14];
    const float* w2 = (const float*)d_in[15];
    const float* b2 = (const float*)d_in[16];
    const float* w3 = (const float*)d_in[17];
    const float* b3 = (const float*)d_in[18];
    const float* w4 = (const float*)d_in[19];
    const float* b4 = (const float*)d_in[20];
    const float* w5 = (const float*)d_in[21];
    const float* b5 = (const float*)d_in[22];

    float *wproj, *t0, *t1, *t2, *t3, *t4, *pL1, *part, *scale, *shift;
    cudaGetSymbolAddress((void**)&wproj, g_wproj);
    cudaGetSymbolAddress((void**)&t0, g_t0);
    cudaGetSymbolAddress((void**)&t1, g_t1);
    cudaGetSymbolAddress((void**)&t2, g_t2);
    cudaGetSymbolAddress((void**)&t3, g_t3);
    cudaGetSymbolAddress((void**)&t4, g_t4);
    cudaGetSymbolAddress((void**)&pL1, g_pL1);
    cudaGetSymbolAddress((void**)&part, g_part);
    cudaGetSymbolAddress((void**)&scale, g_scale);
    cudaGetSymbolAddress((void**)&shift, g_shift);

    // 1) hypernet weights
    {
        int tot = NHEADS * CPROJ * CIN0;
        hyper_kernel<<<(tot + 255) / 256, 256>>>(y_in, tables, wproj);
    }
    // 2) dynamic 1x1x1 projection -> t0 [2,1024,4,6,8]
    {
        dim3 pg(128, BATCH);
        proj_kernel2<<<pg, 192>>>(x_in, wproj, t0);
    }
    // 3) decoder stack
    run_bn(t0, 1024, 4 * 6 * 8, g0, be0, part, scale, shift);
    // L1 split 2-way over Cin into partial buffers, then combine(+bias)
    run_convt9<6, 8, 12, 2, 2, 8, 2, false>(t0, w1, b1, pL1, 1024, 512, 4, 6, 8);
    {
        int OS = 8 * 12 * 16;
        size_t tot = (size_t)BATCH * 512 * OS;
        combine_kernel<<<(unsigned)((tot + 255) / 256), 256>>>(pL1, b1, t1, 512, OS);
    }
    run_bn(t1, 512, 8 * 12 * 16, g1, be1, part, scale, shift);
    run_convt9<4, 16, 24, 2, 2, 8, 1, false>(t1, w2, b2, t2, 512, 256, 8, 12, 16);
    run_bn(t2, 256, 16 * 24 * 32, g2, be2, part, scale, shift);
    run_convt9<8, 16, 24, 1, 2, 8, 1, false>(t2, w3, b3, t3, 256, 128, 16, 24, 32);
    run_bn(t3, 128, 32 * 48 * 64, g3, be3, part, scale, shift);
    run_convt9<8, 16, 24, 1, 2, 8, 1, false>(t3, w4, b4, t4, 128, 32, 32, 48, 64);
    run_bn(t4, 32, 64 * 96 * 128, g4, be4, part, scale, shift);
    run_convt9<8, 16, 24, 1, 1, 32, 1, true>(t4, w5, b5, (float*)d_out, 32, 1,
                                             64, 96, 128);
}